// round 17
// baseline (speedup 1.0000x reference)
#include <cuda_runtime.h>
#include <cstdint>
#include <cstdio>

#define DMODEL 2048
#define NHEADS 16
#define HDIM   128
#define BATCH  2
#define SEQ    2048
#define MROWS  (BATCH*SEQ)   // 4096

// ---------------- scratch (device globals: allocation-free) ----------------
__device__ float g_q[(size_t)MROWS * DMODEL];
__device__ float g_k[(size_t)MROWS * DMODEL];
__device__ float g_v[(size_t)MROWS * DMODEL];
__device__ float g_att[(size_t)MROWS * DMODEL];
// tf32-rounded copies (prepass outputs)
__device__ float g_xq[(size_t)MROWS * DMODEL];
__device__ float g_xk[(size_t)MROWS * DMODEL];
__device__ float g_xv[(size_t)MROWS * DMODEL];
__device__ float g_wq[(size_t)DMODEL * DMODEL];
__device__ float g_wk[(size_t)DMODEL * DMODEL];
__device__ float g_wv[(size_t)DMODEL * DMODEL];
__device__ float g_wo[(size_t)DMODEL * DMODEL];

// ---------------- helpers ----------------
__device__ __forceinline__ uint32_t f2tf(float x) {
    uint32_t r;
    asm("cvt.rna.tf32.f32 %0, %1;" : "=r"(r) : "f"(x));
    return r;
}

__device__ __forceinline__ void mma_tf32(float* c, const uint32_t* a, const uint32_t* b) {
    asm("mma.sync.aligned.m16n8k8.row.col.f32.tf32.tf32.f32 "
        "{%0,%1,%2,%3}, {%4,%5,%6,%7}, {%8,%9}, {%0,%1,%2,%3};"
        : "+f"(c[0]), "+f"(c[1]), "+f"(c[2]), "+f"(c[3])
        : "r"(a[0]), "r"(a[1]), "r"(a[2]), "r"(a[3]),
          "r"(b[0]), "r"(b[1]));
}

__device__ __forceinline__ void ldsm_x4(uint32_t* r, uint32_t addr) {
    asm volatile("ldmatrix.sync.aligned.m8n8.x4.shared.b16 {%0,%1,%2,%3}, [%4];"
        : "=r"(r[0]), "=r"(r[1]), "=r"(r[2]), "=r"(r[3]) : "r"(addr));
}

__device__ __forceinline__ void cpa16(uint32_t dst, const void* src) {
    asm volatile("cp.async.cg.shared.global [%0], [%1], 16;" :: "r"(dst), "l"(src));
}
__device__ __forceinline__ void cpa_commit() {
    asm volatile("cp.async.commit_group;" ::: "memory");
}
__device__ __forceinline__ void cpa_wait0() {
    asm volatile("cp.async.wait_group 0;" ::: "memory");
}
__device__ __forceinline__ void cpa_wait1() {
    asm volatile("cp.async.wait_group 1;" ::: "memory");
}

// ---------------- prepass: tf32 rounding of inputs / weights ----------------
__global__ void __launch_bounds__(256) round_inputs(
    const float* __restrict__ q, const float* __restrict__ k, const float* __restrict__ v,
    float* __restrict__ oq, float* __restrict__ ok, float* __restrict__ ov)
{
    size_t idx = ((size_t)blockIdx.x * 256 + threadIdx.x) * 4;
    const float* s = (blockIdx.y == 0) ? q : (blockIdx.y == 1) ? k : v;
    float*       d = (blockIdx.y == 0) ? oq : (blockIdx.y == 1) ? ok : ov;
    float4 t = *(const float4*)(s + idx);
    uint4 u = make_uint4(f2tf(t.x), f2tf(t.y), f2tf(t.z), f2tf(t.w));
    *(uint4*)(d + idx) = u;
}

__global__ void __launch_bounds__(256) round_weights(
    const float* __restrict__ wq, const float* __restrict__ wk,
    const float* __restrict__ wv, const float* __restrict__ wo,
    float* __restrict__ oq, float* __restrict__ ok,
    float* __restrict__ ov, float* __restrict__ oo)
{
    size_t idx = ((size_t)blockIdx.x * 256 + threadIdx.x) * 4;
    const float* s = (blockIdx.y == 0) ? wq : (blockIdx.y == 1) ? wk : (blockIdx.y == 2) ? wv : wo;
    float*       d = (blockIdx.y == 0) ? oq : (blockIdx.y == 1) ? ok : (blockIdx.y == 2) ? ov : oo;
    float4 t = *(const float4*)(s + idx);
    uint4 u = make_uint4(f2tf(t.x), f2tf(t.y), f2tf(t.z), f2tf(t.w));
    *(uint4*)(d + idx) = u;
}

// ---------------- GEMM body: C = (A @ W^T + bias) * scale ----------------
// CTA tile 128x128, k-tile 32, 8 warps, warp tile 64x32, m16n8k8 tf32.
// cp.async double-buffered smem + register double-buffered fragments
// (ldsm for ks+1 issued during MMAs of ks -> LDSM latency hidden).
#define GT_K 32
#define GLD  36
#define GSTG (128*GLD)
#define GEMM_SMEM_BYTES (4*GSTG*4)   // 73728 B -> 2 CTAs/SM

template<bool ROUND>
__device__ __forceinline__ void gemm_body(
    const float* __restrict__ A, const float* __restrict__ W,
    const float* __restrict__ bias, float* __restrict__ C, float scale)
{
    extern __shared__ uint32_t gsm[];
    const uint32_t sbase = (uint32_t)__cvta_generic_to_shared(gsm);

    const int tid  = threadIdx.x;
    const int ctaN = blockIdx.x * 128;
    const int ctaM = blockIdx.y * 128;

    const int warp = tid >> 5, lane = tid & 31;
    const int g = lane >> 2, tg = lane & 3;
    const int wm = (warp & 1) * 64;
    const int wn = (warp >> 1) * 32;

    const int rowA = wm + (lane & 7) + ((lane & 8) ? 8 : 0);
    const int colA = (lane & 16) ? 4 : 0;
    const int rowB = wn + (lane & 7) + ((lane & 16) ? 8 : 0);
    const int colB = (lane & 8) ? 4 : 0;

    const int lr = tid >> 3;
    const int lc = (tid & 7) * 4;

    const float* Abase = A + (size_t)(ctaM + lr) * DMODEL + lc;
    const float* Wbase = W + (size_t)(ctaN + lr) * DMODEL + lc;

    float acc[4][4][4];
#pragma unroll
    for (int mt = 0; mt < 4; mt++)
#pragma unroll
        for (int nt = 0; nt < 4; nt++)
#pragma unroll
            for (int j = 0; j < 4; j++) acc[mt][nt][j] = 0.f;

    const int nk = DMODEL / GT_K;

    auto issue = [&](int kt, int s) {
        const float* An = Abase + (size_t)kt * GT_K;
        const float* Wn = Wbase + (size_t)kt * GT_K;
        uint32_t dA = sbase + 4u * ((uint32_t)(s * 2 * GSTG) + lr * GLD + lc);
        uint32_t dW = dA + 4u * (uint32_t)GSTG;
#pragma unroll
        for (int p = 0; p < 4; p++) {
            cpa16(dA + 4u * (p * 32 * GLD), An + (size_t)(p * 32) * DMODEL);
            cpa16(dW + 4u * (p * 32 * GLD), Wn + (size_t)(p * 32) * DMODEL);
        }
        cpa_commit();
    };

    issue(0, 0);
    cpa_wait0();
    __syncthreads();

    for (int kt = 0; kt < nk; kt++) {
        const int cur = kt & 1;
        const bool pre = (kt + 1 < nk);
        if (pre) issue(kt + 1, cur ^ 1);

        const uint32_t sA = sbase + (uint32_t)(cur * 2 * GSTG) * 4u;
        const uint32_t sW = sA + (uint32_t)GSTG * 4u;

        // register double-buffered fragments
        uint32_t a[2][4][4];
        uint32_t bfr[2][4][2];

        // preload ks=0 into slot 0
#pragma unroll
        for (int mt = 0; mt < 4; mt++)
            ldsm_x4(a[0][mt], sA + 4u * ((rowA + mt * 16) * GLD + colA));
#pragma unroll
        for (int ntp = 0; ntp < 2; ntp++) {
            uint32_t t[4];
            ldsm_x4(t, sW + 4u * ((rowB + ntp * 16) * GLD + colB));
            bfr[0][2 * ntp][0] = t[0];  bfr[0][2 * ntp][1] = t[1];
            bfr[0][2 * ntp + 1][0] = t[2];  bfr[0][2 * ntp + 1][1] = t[3];
        }

#pragma unroll
        for (int ks = 0; ks < 4; ks++) {
            const int c = ks & 1, n = c ^ 1;
            if (ks < 3) {
                // issue ks+1 fragment loads; consumed after these MMAs
#pragma unroll
                for (int mt = 0; mt < 4; mt++)
                    ldsm_x4(a[n][mt], sA + 4u * ((rowA + mt * 16) * GLD + (ks + 1) * 8 + colA));
#pragma unroll
                for (int ntp = 0; ntp < 2; ntp++) {
                    uint32_t t[4];
                    ldsm_x4(t, sW + 4u * ((rowB + ntp * 16) * GLD + (ks + 1) * 8 + colB));
                    bfr[n][2 * ntp][0] = t[0];  bfr[n][2 * ntp][1] = t[1];
                    bfr[n][2 * ntp + 1][0] = t[2];  bfr[n][2 * ntp + 1][1] = t[3];
                }
            }
#pragma unroll
            for (int mt = 0; mt < 4; mt++)
#pragma unroll
                for (int nt = 0; nt < 4; nt++)
                    mma_tf32(acc[mt][nt], a[c][mt], bfr[c][nt]);
        }

        if (pre) cpa_wait0();
        __syncthreads();
    }

#pragma unroll
    for (int mt = 0; mt < 4; mt++) {
        int r0 = ctaM + wm + mt * 16 + g;
        int r1 = r0 + 8;
#pragma unroll
        for (int nt = 0; nt < 4; nt++) {
            int c = ctaN + wn + nt * 8 + 2 * tg;
            float b0 = bias[c], b1 = bias[c + 1];
            float v00 = (acc[mt][nt][0] + b0) * scale;
            float v01 = (acc[mt][nt][1] + b1) * scale;
            float v10 = (acc[mt][nt][2] + b0) * scale;
            float v11 = (acc[mt][nt][3] + b1) * scale;
            if (ROUND) {
                v00 = __uint_as_float(f2tf(v00));
                v01 = __uint_as_float(f2tf(v01));
                v10 = __uint_as_float(f2tf(v10));
                v11 = __uint_as_float(f2tf(v11));
            }
            *(float2*)&C[(size_t)r0 * DMODEL + c] = make_float2(v00, v01);
            *(float2*)&C[(size_t)r1 * DMODEL + c] = make_float2(v10, v11);
        }
    }
}

__global__ void __launch_bounds__(256, 2) gemm_qkv(
    const float* __restrict__ q_in, const float* __restrict__ k_in, const float* __restrict__ v_in,
    const float* __restrict__ Wq, const float* __restrict__ bq,
    const float* __restrict__ Wk, const float* __restrict__ bk,
    const float* __restrict__ Wv, const float* __restrict__ bv,
    float* __restrict__ Cq, float* __restrict__ Ck, float* __restrict__ Cv,
    float qscale)
{
    const int z = blockIdx.z;
    const float* A   = (z == 0) ? q_in : (z == 1) ? k_in : v_in;
    const float* W   = (z == 0) ? Wq   : (z == 1) ? Wk   : Wv;
    const float* bia = (z == 0) ? bq   : (z == 1) ? bk   : bv;
    float*       C   = (z == 0) ? Cq   : (z == 1) ? Ck   : Cv;
    float        s   = (z == 0) ? qscale : 1.0f;
    gemm_body<true>(A, W, bia, C, s);
}

__global__ void __launch_bounds__(256, 2) gemm_o(
    const float* __restrict__ A, const float* __restrict__ W,
    const float* __restrict__ bias, float* __restrict__ C)
{
    gemm_body<false>(A, W, bias, C, 1.0f);
}

// ---------------- Flash attention v2 (unchanged from R14 best): qtile=64, 2 CTAs/SM ----------------
#define ALD 132   // 128 + 4 pad
#define AK_OFF (64*ALD)
#define AV_OFF (128*ALD)
#define ATT_SMEM_WORDS (192*ALD)
#define ATT_SMEM_BYTES (ATT_SMEM_WORDS * 4)   // 101376 B
#define NKT (SEQ/64)

__global__ void __launch_bounds__(128, 2) attn_kernel(
    const float* __restrict__ Q, const float* __restrict__ Kp,
    const float* __restrict__ Vp, float* __restrict__ O)
{
    extern __shared__ uint32_t sm[];
    uint32_t (*Vs)[ALD] = (uint32_t(*)[ALD])(sm + AV_OFF);

    const uint32_t sbase = (uint32_t)__cvta_generic_to_shared(sm);
    const uint32_t sQ = sbase;
    const uint32_t sK = sbase + 4u * AK_OFF;

    const int tid  = threadIdx.x;
    const int qt = blockIdx.x, h = blockIdx.y, b = blockIdx.z;
    const int warp = tid >> 5, lane = tid & 31, g = lane >> 2, tg = lane & 3;
    const int qbase = warp * 16;

    const int rowAq = qbase + (lane & 7) + ((lane & 8) ? 8 : 0);
    const int colA  = (lane & 16) ? 4 : 0;
    const int rowK  = (lane & 7) + ((lane & 16) ? 8 : 0);
    const int colK  = (lane & 8) ? 4 : 0;
    const int psrc  = (lane & 28) | ((lane >> 1) & 1);

    const size_t rowQ0 = (size_t)(b * SEQ + qt * 64);
    const int colH = h * HDIM;

    const int ldr = tid >> 5;       // 0..3
    const int ldc = lane * 4;       // 0..124 (words)

#pragma unroll
    for (int p = 0; p < 16; p++) {
        int rr = ldr + p * 4;
        cpa16(sQ + 4u * (rr * ALD + ldc), Q + (rowQ0 + rr) * DMODEL + colH + ldc);
    }
    {
        size_t rowK0 = (size_t)(b * SEQ);
#pragma unroll
        for (int p = 0; p < 16; p++) {
            int rr = ldr + p * 4;
            cpa16(sK + 4u * (rr * ALD + ldc), Kp + (rowK0 + rr) * DMODEL + colH + ldc);
            cpa16(sbase + 4u * (AV_OFF + rr * ALD + ldc), Vp + (rowK0 + rr) * DMODEL + colH + ldc);
        }
    }
    cpa_commit();
    cpa_wait0();
    __syncthreads();

    float acc[16][4];
#pragma unroll
    for (int nt = 0; nt < 16; nt++)
#pragma unroll
        for (int j = 0; j < 4; j++) acc[nt][j] = 0.f;

    float m0 = -1e30f, m1 = -1e30f, l0 = 0.f, l1 = 0.f;

    for (int kt = 0; kt < NKT; kt++) {
        const bool pre = (kt + 1 < NKT);
        const size_t rowKn = (size_t)(b * SEQ + (kt + 1) * 64);

        float sf[8][4];
#pragma unroll
        for (int nt = 0; nt < 8; nt++)
#pragma unroll
            for (int j = 0; j < 4; j++) sf[nt][j] = 0.f;

#pragma unroll
        for (int ks = 0; ks < 16; ks++) {
            uint32_t a[4];
            ldsm_x4(a, sQ + 4u * (rowAq * ALD + ks * 8 + colA));
            uint32_t bfr[8][2];
#pragma unroll
            for (int ntp = 0; ntp < 4; ntp++) {
                uint32_t t[4];
                ldsm_x4(t, sK + 4u * ((rowK + ntp * 16) * ALD + ks * 8 + colK));
                bfr[2 * ntp][0] = t[0];  bfr[2 * ntp][1] = t[1];
                bfr[2 * ntp + 1][0] = t[2];  bfr[2 * ntp + 1][1] = t[3];
            }
#pragma unroll
            for (int nt = 0; nt < 8; nt++)
                mma_tf32(sf[nt], a, bfr[nt]);
        }

        __syncthreads();
        if (pre) {
#pragma unroll
            for (int p = 0; p < 16; p++) {
                int rr = ldr + p * 4;
                cpa16(sK + 4u * (rr * ALD + ldc),
                      Kp + (rowKn + rr) * DMODEL + colH + ldc);
            }
            cpa_commit();
            cpa_wait1();
        } else {
            cpa_wait0();
        }
        __syncthreads();

        float tm0 = -1e30f, tm1 = -1e30f;
#pragma unroll
        for (int nt = 0; nt < 8; nt++) {
            tm0 = fmaxf(tm0, fmaxf(sf[nt][0], sf[nt][1]));
            tm1 = fmaxf(tm1, fmaxf(sf[nt][2], sf[nt][3]));
        }
        tm0 = fmaxf(tm0, __shfl_xor_sync(0xffffffffu, tm0, 1));
        tm0 = fmaxf(tm0, __shfl_xor_sync(0xffffffffu, tm0, 2));
        tm1 = fmaxf(tm1, __shfl_xor_sync(0xffffffffu, tm1, 1));
        tm1 = fmaxf(tm1, __shfl_xor_sync(0xffffffffu, tm1, 2));

        float nm0 = fmaxf(m0, tm0), nm1 = fmaxf(m1, tm1);
        float al0 = __expf(m0 - nm0), al1 = __expf(m1 - nm1);

        float ts0 = 0.f, ts1 = 0.f;
#pragma unroll
        for (int nt = 0; nt < 8; nt++) {
            sf[nt][0] = __expf(sf[nt][0] - nm0); ts0 += sf[nt][0];
            sf[nt][1] = __expf(sf[nt][1] - nm0); ts0 += sf[nt][1];
            sf[nt][2] = __expf(sf[nt][2] - nm1); ts1 += sf[nt][2];
            sf[nt][3] = __expf(sf[nt][3] - nm1); ts1 += sf[nt][3];
        }
        ts0 += __shfl_xor_sync(0xffffffffu, ts0, 1);
        ts0 += __shfl_xor_sync(0xffffffffu, ts0, 2);
        ts1 += __shfl_xor_sync(0xffffffffu, ts1, 1);
        ts1 += __shfl_xor_sync(0xffffffffu, ts1, 2);

        l0 = l0 * al0 + ts0;  l1 = l1 * al1 + ts1;
        m0 = nm0;             m1 = nm1;

#pragma unroll
        for (int nt = 0; nt < 16; nt++) {
            acc[nt][0] *= al0; acc[nt][1] *= al0;
            acc[nt][2] *= al1; acc[nt][3] *= al1;
        }

        uint32_t pb[8][4];
#pragma unroll
        for (int nt = 0; nt < 8; nt++) {
            pb[nt][0] = f2tf(sf[nt][0]);
            pb[nt][1] = f2tf(sf[nt][1]);
            pb[nt][2] = f2tf(sf[nt][2]);
            pb[nt][3] = f2tf(sf[nt][3]);
        }

        const bool odd = (tg & 1);
#pragma unroll
        for (int ks = 0; ks < 8; ks++) {
            uint32_t u0 = __shfl_sync(0xffffffffu, pb[ks][0], psrc);
            uint32_t u1 = __shfl_sync(0xffffffffu, pb[ks][1], psrc);
            uint32_t u2 = __shfl_sync(0xffffffffu, pb[ks][2], psrc);
            uint32_t u3 = __shfl_sync(0xffffffffu, pb[ks][3], psrc);
            uint32_t w0 = __shfl_sync(0xffffffffu, pb[ks][0], psrc + 2);
            uint32_t w1 = __shfl_sync(0xffffffffu, pb[ks][1], psrc + 2);
            uint32_t w2 = __shfl_sync(0xffffffffu, pb[ks][2], psrc + 2);
            uint32_t w3 = __shfl_sync(0xffffffffu, pb[ks][3], psrc + 2);
            uint32_t a[4];
            a[0] = odd ? u1 : u0;
            a[1] = odd ? u3 : u2;
            a[2] = odd ? w1 : w0;
            a[3] = odd ? w3 : w2;
#pragma unroll
            for (int nt = 0; nt < 16; nt++) {
                uint32_t bb[2];
                bb[0] = Vs[ks * 8 + tg][nt * 8 + g];
                bb[1] = Vs[ks * 8 + tg + 4][nt * 8 + g];
                mma_tf32(acc[nt], a, bb);
            }
        }

        __syncthreads();
        if (pre) {
#pragma unroll
            for (int p = 0; p < 16; p++) {
                int rr = ldr + p * 4;
                cpa16(sbase + 4u * (AV_OFF + rr * ALD + ldc),
                      Vp + (rowKn + rr) * DMODEL + colH + ldc);
            }
            cpa_commit();
            cpa_wait1();
        } else {
            cpa_wait0();
        }
        __syncthreads();
    }

    float inv0 = 1.f / l0, inv1 = 1.f / l1;
    size_t r0 = rowQ0 + qbase + g;
    size_t r1 = r0 + 8;
#pragma unroll
    for (int nt = 0; nt < 16; nt++) {
        int c = colH + nt * 8 + 2 * tg;
        float2 w0 = make_float2(__uint_as_float(f2tf(acc[nt][0] * inv0)),
                                __uint_as_float(f2tf(acc[nt][1] * inv0)));
        float2 w1 = make_float2(__uint_as_float(f2tf(acc[nt][2] * inv1)),
                                __uint_as_float(f2tf(acc[nt][3] * inv1)));
        *(float2*)&O[r0 * DMODEL + c] = w0;
        *(float2*)&O[r1 * DMODEL + c] = w1;
    }
}

// ---------------- launch ----------------
extern "C" void kernel_launch(void* const* d_in, const int* in_sizes, int n_in,
                              void* d_out, int out_size)
{
    const float* query  = (const float*)d_in[0];
    const float* key_in = (const float*)d_in[1];
    const float* value  = (const float*)d_in[2];
    const float* Wq = (const float*)d_in[3];
    const float* bq = (const float*)d_in[4];
    const float* Wk = (const float*)d_in[5];
    const float* bk = (const float*)d_in[6];
    const float* Wv = (const float*)d_in[7];
    const float* bv = (const float*)d_in[8];
    const float* Wo = (const float*)d_in[9];
    const float* bo = (const float*)d_in[10];
    float* out = (float*)d_out;

    float *gq, *gk, *gv, *ga;
    float *xq, *xk, *xv, *wq, *wk, *wv, *wo;
    cudaGetSymbolAddress((void**)&gq, g_q);
    cudaGetSymbolAddress((void**)&gk, g_k);
    cudaGetSymbolAddress((void**)&gv, g_v);
    cudaGetSymbolAddress((void**)&ga, g_att);
    cudaGetSymbolAddress((void**)&xq, g_xq);
    cudaGetSymbolAddress((void**)&xk, g_xk);
    cudaGetSymbolAddress((void**)&xv, g_xv);
    cudaGetSymbolAddress((void**)&wq, g_wq);
    cudaGetSymbolAddress((void**)&wk, g_wk);
    cudaGetSymbolAddress((void**)&wv, g_wv);
    cudaGetSymbolAddress((void**)&wo, g_wo);

    cudaFuncSetAttribute(attn_kernel,
                         cudaFuncAttributeMaxDynamicSharedMemorySize, ATT_SMEM_BYTES);
    cudaFuncSetAttribute(gemm_qkv,
                         cudaFuncAttributeMaxDynamicSharedMemorySize, GEMM_SMEM_BYTES);
    cudaFuncSetAttribute(gemm_o,
                         cudaFuncAttributeMaxDynamicSharedMemorySize, GEMM_SMEM_BYTES);

    const float qscale = 0.08838834764831845f;   // 1/sqrt(128)

    // prepass: tf32-round inputs + weights
    {
        dim3 gi((MROWS * DMODEL) / (4 * 256), 3);    // (8192, 3)
        round_inputs<<<gi, 256>>>(query, key_in, value, xq, xk, xv);
        dim3 gw((DMODEL * DMODEL) / (4 * 256), 4);   // (4096, 4)
        round_weights<<<gw, 256>>>(Wq, Wk, Wv, Wo, wq, wk, wv, wo);
    }

    dim3 qkv_grid(DMODEL / 128, MROWS / 128, 3);   // (16, 32, 3) = 1536 CTAs
    gemm_qkv<<<qkv_grid, 256, GEMM_SMEM_BYTES>>>(xq, xk, xv,
                                                 wq, bq, wk, bk, wv, bv,
                                                 gq, gk, gv, qscale);

    attn_kernel<<<dim3(SEQ / 64, NHEADS, BATCH), 128, ATT_SMEM_BYTES>>>(gq, gk, gv, ga);

    gemm_o<<<dim3(DMODEL / 128, MROWS / 128), 256, GEMM_SMEM_BYTES>>>(ga, wo, bo, out);
}